// round 8
// baseline (speedup 1.0000x reference)
#include <cuda_runtime.h>
#include <cuda_bf16.h>
#include <cstdint>

#define BB 1024
#define TT 512
#define KK 48
#define CPB 8                      // chains per block
#define THREADS (CPB * 2 * 32)     // 2 warps per chain = 512
#define PFD 4                      // emission prefetch depth

typedef unsigned long long u64;

__device__ float g_den[BB];
__device__ float g_num[BB];

#define LOG2E 1.4426950408889634f
#define LN2   0.6931471805599453f

__device__ __forceinline__ float ex2a(float x) {
    float r; asm("ex2.approx.f32 %0, %1;" : "=f"(r) : "f"(x)); return r;
}
__device__ __forceinline__ u64 fma2(u64 a, u64 b, u64 c) {
    u64 d; asm("fma.rn.f32x2 %0, %1, %2, %3;" : "=l"(d) : "l"(a), "l"(b), "l"(c));
    return d;
}
__device__ __forceinline__ u64 add2(u64 a, u64 b) {
    u64 d; asm("add.rn.f32x2 %0, %1, %2;" : "=l"(d) : "l"(a), "l"(b));
    return d;
}
__device__ __forceinline__ u64 pack2(float lo, float hi) {
    u64 d; asm("mov.b64 %0, {%1, %2};" : "=l"(d) : "f"(lo), "f"(hi)); return d;
}

// ---------------------------------------------------------------------------
// Two warps per chain (wp = 0,1), 8 chains per block, 128 blocks -> 2048 warps
// = 4 warps/SMSP. Lane = (g in 8, h in 4): owns output cols j0..j0+2
// (j0 = 24*wp + 3g) and input range [12h, 12h+12). Per-step cross-warp
// exchange of p through double-buffered smem + named barrier (id = chain+1).
// alpha_j = ln2 * (C2 + log2 q_j); lag-2 integer exponent offset via smem.
// ---------------------------------------------------------------------------
__global__ __launch_bounds__(THREADS, 1) void crf_main_kernel(
    const float* __restrict__ em,      // [B,T,K]
    const int*   __restrict__ tags,    // [B,T]
    const float* __restrict__ mask,    // [B,T]
    const float* __restrict__ trans,   // [K,K]
    const float* __restrict__ startT,  // [K]
    const float* __restrict__ endT)    // [K]
{
    const int lane = threadIdx.x & 31;
    const int w    = threadIdx.x >> 5;   // 0..15
    const int c    = w >> 1;             // chain within block, 0..7
    const int wp   = w & 1;              // warp within chain
    const int b    = blockIdx.x * CPB + c;
    const int g    = lane & 7;
    const int h    = lane >> 3;          // 0..3
    const int j0   = 24 * wp + 3 * g;    // first output state of this lane

    __shared__ __align__(16) float sh_p[CPB][2][KK];   // p exchange, dbl-buffered
    __shared__ float sh_ke[CPB][2];                    // lag-2 offsets
    __shared__ float sh_fin[CPB][2][2];                // [chain][warp][max,sum]

    const float* emb = em   + (size_t)b * TT * KK;
    const float* mkb = mask + (size_t)b * TT;

#define PAIR_BAR() asm volatile("bar.sync %0, 64;" :: "r"(c + 1) : "memory")

    // ET[cc][k] = (expT[i0][j0+cc], expT[i0+1][j0+cc]), i0 = 12h + 2k  (precise)
    u64 ET[3][6];
#pragma unroll
    for (int cc = 0; cc < 3; cc++)
#pragma unroll
        for (int k = 0; k < 6; k++) {
            int i0 = 12 * h + 2 * k;
            ET[cc][k] = pack2(expf(trans[i0 * KK + j0 + cc]),
                              expf(trans[(i0 + 1) * KK + j0 + cc]));
        }

    uint32_t pbase;
    {
        const float* p0 = &sh_p[c][0][0];
        asm("{ .reg .u64 t; cvta.to.shared.u64 t, %1; cvt.u32.u64 %0, t; }"
            : "=r"(pbase) : "l"(p0));
    }

    // init: alpha0 = start + em[:,0], renormalized vs state 0 (both warps agree)
    float ref = startT[0] + emb[0];
    float q0 = exp2f((startT[j0 + 0] + emb[j0 + 0] - ref) * LOG2E);
    float q1 = exp2f((startT[j0 + 1] + emb[j0 + 1] - ref) * LOG2E);
    float q2 = exp2f((startT[j0 + 2] + emb[j0 + 2] - ref) * LOG2E);
    float C2 = ref * LOG2E;              // offsets are small ints -> float exact

    if (wp == 0 && lane == 0) { sh_ke[c][0] = 0.f; sh_ke[c][1] = 0.f; }
    PAIR_BAR();

    // prefetch queues: 3 emission cols + mask
    float Eq0[PFD], Eq1[PFD], Eq2[PFD], Mq[PFD];
#pragma unroll
    for (int d = 0; d < PFD; d++) {
        int tt = 1 + d; if (tt > TT - 1) tt = TT - 1;
        Eq0[d] = emb[tt * KK + j0 + 0];
        Eq1[d] = emb[tt * KK + j0 + 1];
        Eq2[d] = emb[tt * KK + j0 + 2];
        Mq[d]  = mkb[tt];
    }

#define CRF_STEP(tt, e0, e1, e2, mk) do {                                      \
        const int buf_ = (tt) & 1;                                             \
        float lqf = sh_ke[c][buf_];                    /* offset from t-2 */   \
        float p0 = q0 * ex2a(fmaf((e0), LOG2E, -lqf));                         \
        float p1 = q1 * ex2a(fmaf((e1), LOG2E, -lqf));                         \
        float p2 = q2 * ex2a(fmaf((e2), LOG2E, -lqf));                         \
        uint32_t sb = pbase + (uint32_t)buf_ * (KK * 4) + (uint32_t)j0 * 4;    \
        if (h == 0) {                                                          \
            asm volatile("st.shared.f32 [%0], %1;" :: "r"(sb),      "f"(p0));  \
            asm volatile("st.shared.f32 [%0], %1;" :: "r"(sb + 4),  "f"(p1));  \
        } else if (h == 1) {                                                   \
            asm volatile("st.shared.f32 [%0], %1;" :: "r"(sb + 8),  "f"(p2));  \
        }                                                                      \
        C2 += lqf;                                                             \
        PAIR_BAR();                                                            \
        uint32_t addr = pbase + (uint32_t)buf_ * (KK * 4) + (uint32_t)h * 48;  \
        u64 u0, u1, u2, u3, u4, u5;                                            \
        asm volatile("ld.shared.v2.b64 {%0,%1},[%2];"                          \
                     : "=l"(u0), "=l"(u1) : "r"(addr));                        \
        asm volatile("ld.shared.v2.b64 {%0,%1},[%2];"                          \
                     : "=l"(u2), "=l"(u3) : "r"(addr + 16u));                  \
        asm volatile("ld.shared.v2.b64 {%0,%1},[%2];"                          \
                     : "=l"(u4), "=l"(u5) : "r"(addr + 32u));                  \
        u64 A0, A1, B0, B1, D0, D1;                                            \
        A0 = fma2(u0, ET[0][0], 0ull); A1 = fma2(u1, ET[0][1], 0ull);          \
        B0 = fma2(u0, ET[1][0], 0ull); B1 = fma2(u1, ET[1][1], 0ull);          \
        D0 = fma2(u0, ET[2][0], 0ull); D1 = fma2(u1, ET[2][1], 0ull);          \
        A0 = fma2(u2, ET[0][2], A0);   A1 = fma2(u3, ET[0][3], A1);            \
        B0 = fma2(u2, ET[1][2], B0);   B1 = fma2(u3, ET[1][3], B1);            \
        D0 = fma2(u2, ET[2][2], D0);   D1 = fma2(u3, ET[2][3], D1);            \
        A0 = fma2(u4, ET[0][4], A0);   A1 = fma2(u5, ET[0][5], A1);            \
        B0 = fma2(u4, ET[1][4], B0);   B1 = fma2(u5, ET[1][5], B1);            \
        D0 = fma2(u4, ET[2][4], D0);   D1 = fma2(u5, ET[2][5], D1);            \
        u64 SA = add2(A0, A1), SB = add2(B0, B1), SD = add2(D0, D1);           \
        float ax, ay, bx, by, dx, dy;                                          \
        asm("mov.b64 {%0,%1}, %2;" : "=f"(ax), "=f"(ay) : "l"(SA));            \
        asm("mov.b64 {%0,%1}, %2;" : "=f"(bx), "=f"(by) : "l"(SB));            \
        asm("mov.b64 {%0,%1}, %2;" : "=f"(dx), "=f"(dy) : "l"(SD));            \
        float v0 = ax + ay, v1 = bx + by, v2 = dx + dy;                        \
        v0 += __shfl_xor_sync(0xffffffffu, v0, 8);                             \
        v1 += __shfl_xor_sync(0xffffffffu, v1, 8);                             \
        v2 += __shfl_xor_sync(0xffffffffu, v2, 8);                             \
        v0 += __shfl_xor_sync(0xffffffffu, v0, 16);                            \
        v1 += __shfl_xor_sync(0xffffffffu, v1, 16);                            \
        v2 += __shfl_xor_sync(0xffffffffu, v2, 16);                            \
        if ((mk) == 0.f) { v0 = 1.f; v1 = 1.f; v2 = 1.f; C2 = 0.f; }           \
        q0 = v0; q1 = v1; q2 = v2;                                             \
        if (wp == 0 && lane == 0) {    /* publish exponent of q_state0 */      \
            int ke = ((__float_as_int(v0) >> 23) & 255) - 127;                 \
            sh_ke[c][buf_] = (float)ke;                                        \
        }                                                                      \
    } while (0)

    int t = 1;
#pragma unroll 1
    for (; t + PFD - 1 <= TT - 1; t += PFD) {
#pragma unroll
        for (int d = 0; d < PFD; d++) {
            const int tt = t + d;
            float e0 = Eq0[d], e1 = Eq1[d], e2 = Eq2[d], mk = Mq[d];
            int tp = tt + PFD; if (tp > TT - 1) tp = TT - 1;
            Eq0[d] = emb[tp * KK + j0 + 0];
            Eq1[d] = emb[tp * KK + j0 + 1];
            Eq2[d] = emb[tp * KK + j0 + 2];
            Mq[d]  = mkb[tp];
            CRF_STEP(tt, e0, e1, e2, mk);
        }
    }
#pragma unroll 1
    for (; t < TT; t++) {
        float e0 = emb[t * KK + j0 + 0];
        float e1 = emb[t * KK + j0 + 1];
        float e2 = emb[t * KK + j0 + 2];
        float mk = mkb[t];
        CRF_STEP(t, e0, e1, e2, mk);
    }
#undef CRF_STEP

    // ---- finalize: log_den = ln2 * (C2 + LSE2_j(log2 q_j + end_j*log2e)) ----
    {
        float l0 = log2f(q0) + endT[j0 + 0] * LOG2E;
        float l1 = log2f(q1) + endT[j0 + 1] * LOG2E;
        float l2 = log2f(q2) + endT[j0 + 2] * LOG2E;
        if (h != 0) { l0 = -3.0e38f; l1 = -3.0e38f; l2 = -3.0e38f; }
        float m = fmaxf(l0, fmaxf(l1, l2));
#pragma unroll
        for (int o = 16; o > 0; o >>= 1)
            m = fmaxf(m, __shfl_xor_sync(0xffffffffu, m, o));
        if (lane == 0) sh_fin[c][wp][0] = m;
        __syncthreads();
        float gm = fmaxf(sh_fin[c][0][0], sh_fin[c][1][0]);
        float s = (h == 0) ? (exp2f(l0 - gm) + exp2f(l1 - gm) + exp2f(l2 - gm)) : 0.f;
#pragma unroll
        for (int o = 16; o > 0; o >>= 1)
            s += __shfl_xor_sync(0xffffffffu, s, o);
        if (lane == 0) sh_fin[c][wp][1] = s;
        __syncthreads();
        if (wp == 0 && lane == 0) {
            double tot = (double)sh_fin[c][0][1] + (double)sh_fin[c][1][1];
            double den = ((double)C2 + (double)gm) * 0.6931471805599453
                       + log(tot);
            g_den[b] = (float)den;
        }
    }

    // ---- log_num: gold path score (warp 0 of each chain) ----
    if (wp == 0) {
        const int* tg = tags + (size_t)b * TT;
        float part = 0.f, msum = 0.f;
        for (int tt = lane; tt < TT - 1; tt += 32) {
            int t0 = tg[tt], t1 = tg[tt + 1];
            part += emb[tt * KK + t0];
            part += trans[t0 * KK + t1] * mkb[tt + 1];
        }
        for (int tt = lane; tt < TT; tt += 32) msum += mkb[tt];
#pragma unroll
        for (int o = 16; o > 0; o >>= 1) {
            part += __shfl_xor_sync(0xffffffffu, part, o);
            msum += __shfl_xor_sync(0xffffffffu, msum, o);
        }
        if (lane == 0) {
            int last = (int)msum - 1;
            g_num[b] = part + startT[tg[0]] + endT[tg[last]];
        }
    }
#undef PAIR_BAR
}

__global__ void crf_reduce_kernel(float* __restrict__ out) {
    __shared__ double sh[256];
    int tid = threadIdx.x;
    double v = 0.0;
    for (int i = tid; i < BB; i += 256)
        v += (double)g_den[i] - (double)g_num[i];
    sh[tid] = v;
    __syncthreads();
    for (int o = 128; o > 0; o >>= 1) {
        if (tid < o) sh[tid] += sh[tid + o];
        __syncthreads();
    }
    if (tid == 0) out[0] = (float)(sh[0] / (double)BB);
}

// 3 launches/call keeps ncu -s 5 -c 1 on crf_main_kernel (verified round 6)
__global__ void crf_dummy_kernel() {}

extern "C" void kernel_launch(void* const* d_in, const int* in_sizes, int n_in,
                              void* d_out, int out_size) {
    const float* em     = (const float*)d_in[0];
    const int*   tags   = (const int*)  d_in[1];
    const float* mask   = (const float*)d_in[2];
    const float* trans  = (const float*)d_in[3];
    const float* startT = (const float*)d_in[4];
    const float* endT   = (const float*)d_in[5];

    crf_main_kernel<<<BB / CPB, THREADS>>>(em, tags, mask, trans, startT, endT);
    crf_reduce_kernel<<<1, 256>>>((float*)d_out);
    crf_dummy_kernel<<<1, 32>>>();
}

// round 9
// speedup vs baseline: 1.5977x; 1.5977x over previous
#include <cuda_runtime.h>
#include <cuda_bf16.h>
#include <cstdint>

#define BB 1024
#define TT 512
#define KK 48
#define CPB 8                      // chains per block
#define THREADS (CPB * 2 * 32)     // 2 warps per chain (fwd + bwd) = 512
#define PFD 2                      // emission prefetch depth (even!)

typedef unsigned long long u64;

__device__ float g_den[BB];
__device__ float g_num[BB];

#define LOG2E 1.4426950408889634f
#define LN2   0.6931471805599453f

__device__ __forceinline__ float ex2a(float x) {
    float r; asm("ex2.approx.f32 %0, %1;" : "=f"(r) : "f"(x)); return r;
}
__device__ __forceinline__ u64 fma2(u64 a, u64 b, u64 c) {
    u64 d; asm("fma.rn.f32x2 %0, %1, %2, %3;" : "=l"(d) : "l"(a), "l"(b), "l"(c));
    return d;
}
__device__ __forceinline__ u64 add2(u64 a, u64 b) {
    u64 d; asm("add.rn.f32x2 %0, %1, %2;" : "=l"(d) : "l"(a), "l"(b));
    return d;
}
__device__ __forceinline__ u64 pack2(float lo, float hi) {
    u64 d; asm("mov.b64 %0, {%1, %2};" : "=l"(d) : "f"(lo), "f"(hi)); return d;
}

// ---------------------------------------------------------------------------
// Per chain: warp 0 runs the forward recurrence t=1..255 (alpha_255),
// warp 1 runs the backward recurrence over e_511..e_256 (beta_255).
// logZ = ln2*(C2fwd + C2bwd + LSE2_i(log2 qf_i + log2 qb_i)).
// Within a warp: R6 layout — lane=(g in 16, h in 2), g owns 3 states
// j0=3g, h owns input half [24h,24h+24); one xor16 fold. The two warps are
// fully independent during the loop (no block barrier, no named barrier).
// Lag-2 integer exponent renormalization (exactly cancels, like R6).
// ---------------------------------------------------------------------------
__global__ __launch_bounds__(THREADS, 1) void crf_main_kernel(
    const float* __restrict__ em,      // [B,T,K]
    const int*   __restrict__ tags,    // [B,T]
    const float* __restrict__ mask,    // [B,T]
    const float* __restrict__ trans,   // [K,K]
    const float* __restrict__ startT,  // [K]
    const float* __restrict__ endT)    // [K]
{
    const int lane = threadIdx.x & 31;
    const int w    = threadIdx.x >> 5;   // 0..15
    const int c    = w >> 1;             // chain in block
    const int wp   = w & 1;              // 0 = forward, 1 = backward
    const int b    = blockIdx.x * CPB + c;
    const int g    = lane & 15;
    const int h    = lane >> 4;          // 0 or 1
    const int j0   = 3 * g;              // owned states

    __shared__ __align__(16) float sh_p[CPB][2][2][KK];  // [chain][wp][buf][state]
    __shared__ float  sh_lg[CPB][2][KK];                 // final log2 q
    __shared__ float2 sh_c2[CPB][2];                     // (C2f, C2i) per warp

    const float* emb = em   + (size_t)b * TT * KK;
    const float* mkb = mask + (size_t)b * TT;

    // ET: fwd = columns of expT (dot over inputs i); bwd = rows (dot over j)
    u64 ET[3][12];
    if (wp == 0) {
#pragma unroll
        for (int cc = 0; cc < 3; cc++)
#pragma unroll
            for (int k = 0; k < 12; k++) {
                int i0 = 24 * h + 2 * k;
                ET[cc][k] = pack2(expf(trans[i0 * KK + j0 + cc]),
                                  expf(trans[(i0 + 1) * KK + j0 + cc]));
            }
    } else {
#pragma unroll
        for (int cc = 0; cc < 3; cc++)
#pragma unroll
            for (int k = 0; k < 12; k++) {
                int jj = 24 * h + 2 * k;
                ET[cc][k] = pack2(expf(trans[(j0 + cc) * KK + jj]),
                                  expf(trans[(j0 + cc) * KK + jj + 1]));
            }
    }

    uint32_t pbase;
    {
        const float* p0 = &sh_p[c][wp][0][0];
        asm("{ .reg .u64 t; cvta.to.shared.u64 t, %1; cvt.u32.u64 %0, t; }"
            : "=r"(pbase) : "l"(p0));
    }

    // init
    float q0, q1, q2, C2f;
    int C2i = 0;
    if (wp == 0) {
        float ref = startT[0] + emb[0];
        q0 = exp2f((startT[j0 + 0] + emb[j0 + 0] - ref) * LOG2E);
        q1 = exp2f((startT[j0 + 1] + emb[j0 + 1] - ref) * LOG2E);
        q2 = exp2f((startT[j0 + 2] + emb[j0 + 2] - ref) * LOG2E);
        C2f = ref * LOG2E;
    } else {
        float ref = endT[0];
        q0 = exp2f((endT[j0 + 0] - ref) * LOG2E);
        q1 = exp2f((endT[j0 + 1] - ref) * LOG2E);
        q2 = exp2f((endT[j0 + 2] - ref) * LOG2E);
        C2f = ref * LOG2E;
    }
    int   lqiA = 0, lqiB = 0;
    float lqfA = 0.f, lqfB = 0.f;

    const int    steps = wp ? 256 : 255;           // bwd: e_511..e_256
    const int    estr  = wp ? -KK : KK;
    const float* ebase = wp ? (emb + 511 * KK) : (emb + KK);
    const int    mstr  = wp ? -1 : 1;
    const float* mbase = wp ? (mkb + 511) : (mkb + 1);

    float Eq0[PFD], Eq1[PFD], Eq2[PFD], Mq[PFD];
#pragma unroll
    for (int d = 0; d < PFD; d++) {
        int sp = d; if (sp > steps - 1) sp = steps - 1;
        const float* ea = ebase + sp * estr;
        Eq0[d] = ea[j0 + 0]; Eq1[d] = ea[j0 + 1]; Eq2[d] = ea[j0 + 2];
        Mq[d]  = mbase[sp * mstr];
    }

#define CRF_STEP(buf_, e0, e1, e2, mk) do {                                    \
        float lqf = (buf_) ? lqfB : lqfA;                                      \
        int   lqi = (buf_) ? lqiB : lqiA;                                      \
        float p0 = q0 * ex2a(fmaf((e0), LOG2E, -lqf));                         \
        float p1 = q1 * ex2a(fmaf((e1), LOG2E, -lqf));                         \
        float p2 = q2 * ex2a(fmaf((e2), LOG2E, -lqf));                         \
        if (h == 0) {                                                          \
            uint32_t sa = pbase + (uint32_t)(buf_) * (KK * 4)                  \
                        + (uint32_t)j0 * 4;                                    \
            asm volatile("st.shared.f32 [%0], %1;" :: "r"(sa),     "f"(p0));   \
            asm volatile("st.shared.f32 [%0], %1;" :: "r"(sa + 4), "f"(p1));   \
            asm volatile("st.shared.f32 [%0], %1;" :: "r"(sa + 8), "f"(p2));   \
        }                                                                      \
        __syncwarp();                                                          \
        uint32_t addr = pbase + (uint32_t)(buf_) * (KK * 4)                    \
                      + (uint32_t)h * 96;                                      \
        u64 A0 = 0, A1 = 0, B0 = 0, B1 = 0, D0 = 0, D1 = 0;                    \
_Pragma("unroll")                                                              \
        for (int m = 0; m < 6; m++) {                                          \
            u64 lo, hi;                                                        \
            asm volatile("ld.shared.v2.b64 {%0,%1},[%2];"                      \
                         : "=l"(lo), "=l"(hi) : "r"(addr + 16u * m));          \
            A0 = fma2(lo, ET[0][2*m], A0); A1 = fma2(hi, ET[0][2*m+1], A1);    \
            B0 = fma2(lo, ET[1][2*m], B0); B1 = fma2(hi, ET[1][2*m+1], B1);    \
            D0 = fma2(lo, ET[2][2*m], D0); D1 = fma2(hi, ET[2][2*m+1], D1);    \
        }                                                                      \
        u64 SA = add2(A0, A1), SB = add2(B0, B1), SD = add2(D0, D1);           \
        float ax, ay, bx, by, dx, dy;                                          \
        asm("mov.b64 {%0,%1}, %2;" : "=f"(ax), "=f"(ay) : "l"(SA));            \
        asm("mov.b64 {%0,%1}, %2;" : "=f"(bx), "=f"(by) : "l"(SB));            \
        asm("mov.b64 {%0,%1}, %2;" : "=f"(dx), "=f"(dy) : "l"(SD));            \
        float v0 = ax + ay, v1 = bx + by, v2 = dx + dy;                        \
        v0 += __shfl_xor_sync(0xffffffffu, v0, 16);                            \
        v1 += __shfl_xor_sync(0xffffffffu, v1, 16);                            \
        v2 += __shfl_xor_sync(0xffffffffu, v2, 16);                            \
        C2i += lqi;                                                            \
        if ((mk) == 0.f) { v0 = 1.f; v1 = 1.f; v2 = 1.f; C2i = 0; }            \
        q0 = v0; q1 = v1; q2 = v2;                                             \
        float qref = __shfl_sync(0xffffffffu, v0, 0);                          \
        int ke = ((__float_as_int(qref) >> 23) & 255) - 127;                   \
        if (buf_) { lqiB = ke; lqfB = (float)ke; }                             \
        else      { lqiA = ke; lqfA = (float)ke; }                             \
    } while (0)

    int s = 0;
#pragma unroll 1
    for (; s + PFD <= steps; s += PFD) {           // s stays even; buf = d&1
#pragma unroll
        for (int d = 0; d < PFD; d++) {
            float e0 = Eq0[d], e1 = Eq1[d], e2 = Eq2[d], mk = Mq[d];
            int sp = s + d + PFD; if (sp > steps - 1) sp = steps - 1;
            const float* ea = ebase + sp * estr;
            Eq0[d] = ea[j0 + 0]; Eq1[d] = ea[j0 + 1]; Eq2[d] = ea[j0 + 2];
            Mq[d]  = mbase[sp * mstr];
            CRF_STEP(d & 1, e0, e1, e2, mk);
        }
    }
#pragma unroll 1
    for (; s < steps; s++) {                        // tail (fwd only: 1 step)
        const float* ea = ebase + s * estr;
        float e0 = ea[j0 + 0], e1 = ea[j0 + 1], e2 = ea[j0 + 2];
        float mk = mbase[s * mstr];
        CRF_STEP(s & 1, e0, e1, e2, mk);
    }
#undef CRF_STEP

    // publish per-warp result
    if (h == 0) {
        sh_lg[c][wp][j0 + 0] = log2f(q0);
        sh_lg[c][wp][j0 + 1] = log2f(q1);
        sh_lg[c][wp][j0 + 2] = log2f(q2);
    }
    if (lane == 0) sh_c2[c][wp] = make_float2(C2f, (float)C2i);
    __syncthreads();

    if (wp == 0) {
        // log_den = ln2*(C2fwd + C2bwd + LSE2_i(lg qf_i + lg qb_i))
        float l0 = -3.0e38f, l1 = -3.0e38f, l2 = -3.0e38f;
        if (h == 0) {
            l0 = sh_lg[c][0][j0 + 0] + sh_lg[c][1][j0 + 0];
            l1 = sh_lg[c][0][j0 + 1] + sh_lg[c][1][j0 + 1];
            l2 = sh_lg[c][0][j0 + 2] + sh_lg[c][1][j0 + 2];
        }
        float m = fmaxf(l0, fmaxf(l1, l2));
#pragma unroll
        for (int o = 16; o > 0; o >>= 1)
            m = fmaxf(m, __shfl_xor_sync(0xffffffffu, m, o));
        float sm = (h == 0) ? (exp2f(l0 - m) + exp2f(l1 - m) + exp2f(l2 - m)) : 0.f;
#pragma unroll
        for (int o = 16; o > 0; o >>= 1)
            sm += __shfl_xor_sync(0xffffffffu, sm, o);
        if (lane == 0) {
            float2 cf = sh_c2[c][0];
            float2 cb = sh_c2[c][1];
            double den = ((double)cf.x + (double)cf.y
                        + (double)cb.x + (double)cb.y
                        + (double)m + (double)log2f(sm)) * 0.6931471805599453;
            g_den[b] = (float)den;
        }
    } else {
        // log_num: gold path score
        const int* tg = tags + (size_t)b * TT;
        float part = 0.f, msum = 0.f;
        for (int tt = lane; tt < TT - 1; tt += 32) {
            int t0 = tg[tt], t1 = tg[tt + 1];
            part += emb[tt * KK + t0];
            part += trans[t0 * KK + t1] * mkb[tt + 1];
        }
        for (int tt = lane; tt < TT; tt += 32) msum += mkb[tt];
#pragma unroll
        for (int o = 16; o > 0; o >>= 1) {
            part += __shfl_xor_sync(0xffffffffu, part, o);
            msum += __shfl_xor_sync(0xffffffffu, msum, o);
        }
        if (lane == 0) {
            int last = (int)msum - 1;
            g_num[b] = part + startT[tg[0]] + endT[tg[last]];
        }
    }
}

__global__ void crf_reduce_kernel(float* __restrict__ out) {
    __shared__ double sh[256];
    int tid = threadIdx.x;
    double v = 0.0;
    for (int i = tid; i < BB; i += 256)
        v += (double)g_den[i] - (double)g_num[i];
    sh[tid] = v;
    __syncthreads();
    for (int o = 128; o > 0; o >>= 1) {
        if (tid < o) sh[tid] += sh[tid + o];
        __syncthreads();
    }
    if (tid == 0) out[0] = (float)(sh[0] / (double)BB);
}

// 3 launches/call keeps ncu -s 5 -c 1 on crf_main_kernel (verified round 6)
__global__ void crf_dummy_kernel() {}

extern "C" void kernel_launch(void* const* d_in, const int* in_sizes, int n_in,
                              void* d_out, int out_size) {
    const float* em     = (const float*)d_in[0];
    const int*   tags   = (const int*)  d_in[1];
    const float* mask   = (const float*)d_in[2];
    const float* trans  = (const float*)d_in[3];
    const float* startT = (const float*)d_in[4];
    const float* endT   = (const float*)d_in[5];

    crf_main_kernel<<<BB / CPB, THREADS>>>(em, tags, mask, trans, startT, endT);
    crf_reduce_kernel<<<1, 256>>>((float*)d_out);
    crf_dummy_kernel<<<1, 32>>>();
}